// round 1
// baseline (speedup 1.0000x reference)
#include <cuda_runtime.h>

#define POOL_M 60
#define NC     256
#define HW     3136
#define CHW    (NC * HW)        // 802816
#define NB     64
#define EPSN   1e-8f

// weights / means scratch (no allocation allowed -> __device__ globals)
__device__ float g_mavg[POOL_M * NC];
__device__ float g_w[NB * POOL_M];

// ---------------------------------------------------------------------------
// Kernel 1: mean over H*W for each (m, c) row.  Pure HBM stream, 192.7 MB.
// One block of 256 threads per row of 3136 floats (784 float4).
// ---------------------------------------------------------------------------
__global__ void mean_kernel(const float* __restrict__ pool) {
    const int row = blockIdx.x;  // m*256 + c, 0..15359
    const float4* p = reinterpret_cast<const float4*>(pool + (size_t)row * HW);
    float s = 0.f;
    for (int i = threadIdx.x; i < HW / 4; i += blockDim.x) {
        float4 v = p[i];
        s += (v.x + v.y) + (v.z + v.w);
    }
    __shared__ float red[8];
    #pragma unroll
    for (int o = 16; o > 0; o >>= 1) s += __shfl_down_sync(0xffffffffu, s, o);
    if ((threadIdx.x & 31) == 0) red[threadIdx.x >> 5] = s;
    __syncthreads();
    if (threadIdx.x < 8) {
        float t = red[threadIdx.x];
        #pragma unroll
        for (int o = 4; o > 0; o >>= 1) t += __shfl_down_sync(0xffu, t, o);
        if (threadIdx.x == 0) g_mavg[row] = t * (1.0f / (float)HW);
    }
}

// ---------------------------------------------------------------------------
// Kernel 2: cosine similarities + softmax -> weights g_w[b][m].
// One block per query b, 256 threads (one per channel). Tiny.
// ---------------------------------------------------------------------------
__device__ __forceinline__ float blockReduce256(float v, float* red) {
    #pragma unroll
    for (int o = 16; o > 0; o >>= 1) v += __shfl_down_sync(0xffffffffu, v, o);
    if ((threadIdx.x & 31) == 0) red[threadIdx.x >> 5] = v;
    __syncthreads();
    float t = 0.f;
    if (threadIdx.x < 8) {
        t = red[threadIdx.x];
        #pragma unroll
        for (int o = 4; o > 0; o >>= 1) t += __shfl_down_sync(0xffu, t, o);
    }
    __syncthreads();   // red will be reused
    return t;          // valid on thread 0
}

__global__ void cosw_kernel(const float* __restrict__ query) {
    const int b = blockIdx.x;
    const int t = threadIdx.x;
    __shared__ float red[8];
    __shared__ float s_cos[POOL_M];
    __shared__ float s_qn;

    const float qv = query[b * NC + t];
    float qn2 = blockReduce256(qv * qv, red);
    if (t == 0) s_qn = fmaxf(sqrtf(qn2), EPSN);
    __syncthreads();

    for (int m = 0; m < POOL_M; m++) {
        const float mv = g_mavg[m * NC + t];
        float d  = blockReduce256(qv * mv, red);
        float n2 = blockReduce256(mv * mv, red);
        if (t == 0) s_cos[m] = d / (s_qn * fmaxf(sqrtf(n2), EPSN));
        __syncthreads();
    }

    if (t == 0) {
        float mx = -1e30f;
        #pragma unroll
        for (int m = 0; m < POOL_M; m++) mx = fmaxf(mx, s_cos[m]);
        float sum = 0.f;
        float e[POOL_M];
        #pragma unroll
        for (int m = 0; m < POOL_M; m++) { e[m] = __expf(s_cos[m] - mx); sum += e[m]; }
        const float inv = 1.0f / sum;
        #pragma unroll
        for (int m = 0; m < POOL_M; m++) g_w[b * POOL_M + m] = e[m] * inv;
    }
}

// ---------------------------------------------------------------------------
// Kernel 3: out[b, pos] = sum_m w[b,m] * pool[m, pos]
// Block = 256 threads = 4 b-groups x 64 lanes; thread = 4 positions x 16 b.
// fma.rn.f32x2 (FFMA2) packed math; weights staged in smem as (w,w) pairs.
// ---------------------------------------------------------------------------
__global__ void __launch_bounds__(256, 2)
wsum_kernel(const float* __restrict__ pool, float* __restrict__ out) {
    __shared__ unsigned long long sw[POOL_M * NB];   // [m][b], duplicated pairs, 30 KB
    const int tid = threadIdx.x;
    for (int i = tid; i < POOL_M * NB; i += 256) {
        const int m = i >> 6, bb = i & 63;
        const unsigned int wb = __float_as_uint(g_w[bb * POOL_M + m]);
        sw[i] = ((unsigned long long)wb << 32) | wb;
    }
    __syncthreads();

    const int group  = tid >> 6;          // 0..3
    const int lane64 = tid & 63;
    const long long posbase = (long long)blockIdx.x * 256 + lane64 * 4;
    const int b0 = group * 16;

    unsigned long long acc[16][2];
    #pragma unroll
    for (int j = 0; j < 16; j++) { acc[j][0] = 0ull; acc[j][1] = 0ull; }

    const ulonglong2* pv = reinterpret_cast<const ulonglong2*>(pool);
    #pragma unroll 4
    for (int m = 0; m < POOL_M; m++) {
        const ulonglong2 p = pv[((long long)m * CHW + posbase) >> 2];
        #pragma unroll
        for (int j = 0; j < 16; j++) {
            const unsigned long long w2 = sw[(m << 6) + b0 + j];
            asm("fma.rn.f32x2 %0, %1, %2, %0;" : "+l"(acc[j][0]) : "l"(p.x), "l"(w2));
            asm("fma.rn.f32x2 %0, %1, %2, %0;" : "+l"(acc[j][1]) : "l"(p.y), "l"(w2));
        }
    }

    ulonglong2* ov = reinterpret_cast<ulonglong2*>(out);
    #pragma unroll
    for (int j = 0; j < 16; j++) {
        ulonglong2 r; r.x = acc[j][0]; r.y = acc[j][1];
        ov[((long long)(b0 + j) * CHW + posbase) >> 2] = r;
    }
}

// ---------------------------------------------------------------------------
extern "C" void kernel_launch(void* const* d_in, const int* in_sizes, int n_in,
                              void* d_out, int out_size) {
    const float* pool  = (const float*)d_in[0];   // [60,256,56,56]
    const float* query = (const float*)d_in[1];   // [64,256]
    float* out = (float*)d_out;                   // [64,256,56,56]

    mean_kernel<<<POOL_M * NC, 256>>>(pool);
    cosw_kernel<<<NB, 256>>>(query);
    wsum_kernel<<<CHW / 256, 256>>>(pool, out);
}